// round 16
// baseline (speedup 1.0000x reference)
#include <cuda_runtime.h>
#include <cuda_bf16.h>
#include <math.h>
#include <stdint.h>

#define BATCH 16384
#define SEQ   50
#define DIM   300
#define HID   32
#define OUTC  2
#define VOCAB 400000

// allocation-free scratch
__device__ uint32_t g_E2[(size_t)VOCAB * (HID / 2)];   // bf16x2 table, 25.6 MB
__device__ float4   g_part[148];                       // per-CTA {m0,m1,s0,s1}
// epoch barriers: counters self-reset, epochs grow monotonically across replays
__device__ unsigned g_cnt1, g_epoch1, g_cnt2, g_epoch2;

#define TILE_R     32
#define KSTEPS     38
#define NT32       (VOCAB / TILE_R)          // 12500 tiles
#define GRID       148
#define NSTAGE     5
#define TILE_ELEMS (TILE_R * DIM)            // 9600 floats
#define TILE_BYTES (TILE_ELEMS * 4)          // 38400 B
#define PAD_ELEMS  16
#define MBAR_OFF   (NSTAGE * TILE_ELEMS + PAD_ELEMS)
#define SMEM_BYTES ((MBAR_OFF + 20) * 4)

__device__ __forceinline__ uint32_t smem_u32(const void* p) {
    return (uint32_t)__cvta_generic_to_shared(p);
}
__device__ __forceinline__ void mbar_init(uint32_t mbar, uint32_t cnt) {
    asm volatile("mbarrier.init.shared::cta.b64 [%0], %1;" :: "r"(mbar), "r"(cnt) : "memory");
}
__device__ __forceinline__ void mbar_expect_tx(uint32_t mbar, uint32_t bytes) {
    asm volatile("mbarrier.arrive.expect_tx.shared::cta.b64 _, [%0], %1;"
                 :: "r"(mbar), "r"(bytes) : "memory");
}
__device__ __forceinline__ void mbar_arrive(uint32_t mbar) {
    asm volatile("mbarrier.arrive.release.cta.shared::cta.b64 _, [%0];"
                 :: "r"(mbar) : "memory");
}
__device__ __forceinline__ void mbar_wait(uint32_t mbar, uint32_t parity) {
    asm volatile(
        "{\n\t"
        ".reg .pred P;\n\t"
        "WAIT_%=: \n\t"
        "mbarrier.try_wait.parity.acquire.cta.shared::cta.b64 P, [%0], %1, 0x989680;\n\t"
        "@P bra.uni DONE_%=;\n\t"
        "bra.uni WAIT_%=;\n\t"
        "DONE_%=: \n\t"
        "}"
        :: "r"(mbar), "r"(parity) : "memory");
}
__device__ __forceinline__ uint64_t policy_evict_first() {
    uint64_t pol;
    asm("createpolicy.fractional.L2::evict_first.b64 %0, 1.0;" : "=l"(pol));
    return pol;
}
__device__ __forceinline__ uint64_t policy_evict_last() {
    uint64_t pol;
    asm("createpolicy.fractional.L2::evict_last.b64 %0, 1.0;" : "=l"(pol));
    return pol;
}
__device__ __forceinline__ void bulk_copy_hint(uint32_t dst, const void* src,
                                               uint32_t bytes, uint32_t mbar,
                                               uint64_t pol) {
    asm volatile(
        "cp.async.bulk.shared::cta.global.mbarrier::complete_tx::bytes.L2::cache_hint "
        "[%0], [%1], %2, [%3], %4;"
        :: "r"(dst), "l"(src), "r"(bytes), "r"(mbar), "l"(pol) : "memory");
}
__device__ __forceinline__ void st_hint(uint32_t* p, uint32_t v, uint64_t pol) {
    asm volatile("st.global.L2::cache_hint.b32 [%0], %1, %2;"
                 :: "l"(p), "r"(v), "l"(pol) : "memory");
}
__device__ __forceinline__ void mma_tf32(
    float acc[4], uint32_t a0, uint32_t a1, uint32_t a2, uint32_t a3,
    uint32_t b0, uint32_t b1)
{
    asm volatile(
        "mma.sync.aligned.m16n8k8.row.col.f32.tf32.tf32.f32 "
        "{%0,%1,%2,%3}, {%4,%5,%6,%7}, {%8,%9}, {%0,%1,%2,%3};\n"
        : "+f"(acc[0]), "+f"(acc[1]), "+f"(acc[2]), "+f"(acc[3])
        : "r"(a0), "r"(a1), "r"(a2), "r"(a3), "r"(b0), "r"(b1));
}
__device__ __forceinline__ uint32_t pack_bf16x2(float lo, float hi) {
    __nv_bfloat162 v = __float22bfloat162_rn(make_float2(lo, hi));
    return *reinterpret_cast<uint32_t*>(&v);
}

// Epoch-based grid barrier (cooperative-groups pattern). All 148 CTAs are
// co-resident (1/SM) so the spin cannot deadlock. Epoch is monotonic across
// graph replays; the counter self-resets -> no per-launch reset needed.
__device__ __forceinline__ void grid_barrier(unsigned* cnt, unsigned* epoch) {
    __syncthreads();
    if (threadIdx.x == 0) {
        __threadfence();                                 // release my CTA's stores
        unsigned e = *(volatile unsigned*)epoch;         // capture BEFORE arriving
        unsigned old = atomicAdd(cnt, 1u);
        if (old == GRID - 1) {
            *cnt = 0;                                    // safe: all have arrived
            __threadfence();
            atomicAdd(epoch, 1u);
        } else {
            while (*(volatile unsigned*)epoch == e) __nanosleep(64);
        }
        __threadfence();                                 // acquire peers' stores
    }
    __syncthreads();
}

// ---------------------------------------------------------------------------
// Fused kernel: project (tf32 mma, 5-stage TMA ring) -> grid barrier ->
// gather+head+per-CTA LSE partial -> grid barrier -> redundant global LSE
// reduce (identical fixed order in every CTA -> deterministic) + apply.
// ---------------------------------------------------------------------------
__global__ __launch_bounds__(256) void dan_fused(
    const float* __restrict__ emb,
    const float* __restrict__ Vw,
    const int*   __restrict__ tokens,
    const float* __restrict__ Vb,
    const float* __restrict__ Ww,
    const float* __restrict__ Wb,
    float*       __restrict__ out)
{
    extern __shared__ float smem[];
    __shared__ float4 sPart[8];
    __shared__ float  sLse[2];

    const uint32_t mbarBase  = smem_u32(smem + MBAR_OFF);   // full[0..4]
    const uint32_t emptyBase = mbarBase + NSTAGE * 8;       // empty[0..4]

    const int tid  = threadIdx.x;
    const int warp = tid >> 5;
    const int lane = tid & 31;
    const int g4   = lane >> 2;
    const int tg   = lane & 3;
    const int bid  = blockIdx.x;

    // ===================== Phase 1: project =====================
    {
        const int warpRow = warp >> 2;
        const int colQuad = warp & 3;
        const int aRow    = warpRow * 16 + g4;

        const uint64_t polF = policy_evict_first();
        const uint64_t polL = policy_evict_last();

        if (tid == 0) {
            #pragma unroll
            for (int i = 0; i < NSTAGE; i++) {
                mbar_init(mbarBase  + i * 8, 1);
                mbar_init(emptyBase + i * 8, 8);
            }
            asm volatile("fence.proxy.async.shared::cta;" ::: "memory");
        }
        if (tid < PAD_ELEMS)
            smem[NSTAGE * TILE_ELEMS + tid] = 0.0f;
        __syncthreads();

        if (tid == 0) {
            #pragma unroll
            for (int s = 0; s < NSTAGE; s++) {
                int tt = bid + s * GRID;
                if (tt < NT32) {
                    mbar_expect_tx(mbarBase + s * 8, TILE_BYTES);
                    bulk_copy_hint(smem_u32(smem + s * TILE_ELEMS),
                                   emb + (size_t)tt * TILE_ELEMS, TILE_BYTES,
                                   mbarBase + s * 8, polF);
                }
            }
        }

        // B fragments straight from gmem into registers (once)
        uint2 breg[KSTEPS];
        {
            const int n = colQuad * 8 + g4;
            const float* vwr = Vw + n * DIM;
            #pragma unroll
            for (int ks = 0; ks < KSTEPS; ks++) {
                int k = ks * 8 + tg;
                breg[ks].x = (k     < DIM) ? __float_as_uint(vwr[k])     : 0u;
                breg[ks].y = (k + 4 < DIM) ? __float_as_uint(vwr[k + 4]) : 0u;
            }
        }

        uint32_t ph0 = 0, ph1 = 0, ph2 = 0, ph3 = 0, ph4 = 0;
        uint32_t pe0 = 0, pe1 = 0, pe2 = 0, pe3 = 0, pe4 = 0;

        int t = bid;
        while (t < NT32) {
            #pragma unroll
            for (int s = 0; s < NSTAGE; s++) {
                if (t < NT32) {
                    const uint32_t fullb  = mbarBase  + s * 8;
                    const uint32_t emptyb = emptyBase + s * 8;

                    uint32_t phv = (s == 0) ? ph0 : (s == 1) ? ph1 : (s == 2) ? ph2
                                 : (s == 3) ? ph3 : ph4;
                    mbar_wait(fullb, phv);
                    if      (s == 0) ph0 ^= 1;
                    else if (s == 1) ph1 ^= 1;
                    else if (s == 2) ph2 ^= 1;
                    else if (s == 3) ph3 ^= 1;
                    else             ph4 ^= 1;

                    const uint32_t* A =
                        (const uint32_t*)(smem + s * TILE_ELEMS) + aRow * DIM + tg;

                    float accE[4] = {0.f, 0.f, 0.f, 0.f};
                    float accO[4] = {0.f, 0.f, 0.f, 0.f};

                    #pragma unroll
                    for (int ks = 0; ks < KSTEPS; ks += 2) {
                        {
                            const uint32_t* Ap = A + ks * 8;
                            mma_tf32(accE, Ap[0], Ap[8 * DIM], Ap[4], Ap[8 * DIM + 4],
                                     breg[ks].x, breg[ks].y);
                        }
                        {
                            const uint32_t* Ap = A + (ks + 1) * 8;
                            mma_tf32(accO, Ap[0], Ap[8 * DIM], Ap[4], Ap[8 * DIM + 4],
                                     breg[ks + 1].x, breg[ks + 1].y);
                        }
                    }

                    if (lane == 0) mbar_arrive(emptyb);

                    int r0  = t * TILE_R + warpRow * 16 + g4;
                    int cp  = colQuad * 4 + tg;
                    st_hint(&g_E2[(size_t)r0 * (HID / 2) + cp],
                            pack_bf16x2(accE[0] + accO[0], accE[1] + accO[1]), polL);
                    st_hint(&g_E2[(size_t)(r0 + 8) * (HID / 2) + cp],
                            pack_bf16x2(accE[2] + accO[2], accE[3] + accO[3]), polL);

                    int tload = t + NSTAGE * GRID;
                    if (tid == 0 && tload < NT32) {
                        uint32_t pev = (s == 0) ? pe0 : (s == 1) ? pe1 : (s == 2) ? pe2
                                     : (s == 3) ? pe3 : pe4;
                        mbar_wait(emptyb, pev);
                        if      (s == 0) pe0 ^= 1;
                        else if (s == 1) pe1 ^= 1;
                        else if (s == 2) pe2 ^= 1;
                        else if (s == 3) pe3 ^= 1;
                        else             pe4 ^= 1;
                        mbar_expect_tx(fullb, TILE_BYTES);
                        bulk_copy_hint(smem_u32(smem + s * TILE_ELEMS),
                                       emb + (size_t)tload * TILE_ELEMS, TILE_BYTES,
                                       fullb, polF);
                    }
                    t += GRID;
                }
            }
        }
    }

    // ===================== Barrier 1: E2 complete =====================
    grid_barrier(&g_cnt1, &g_epoch1);

    // ===================== Phase 2: gather + head + partial LSE ==========
    {
        const int grp = lane >> 3;
        const int hp  = lane & 7;
        const uint2* E2v = (const uint2*)g_E2;

        // per-warp online LSE (meaningful at lane 0; fixed order -> determ.)
        float m0 = -1e30f, m1 = -1e30f, ss0 = 0.f, ss1 = 0.f;

        // warp w of CTA c handles rows c + (w + 8k)*148 — exact cover
        for (int b = bid + warp * GRID; b < BATCH; b += 8 * GRID) {
            int t0 = tokens[b * SEQ + lane];
            int t1 = (lane < SEQ - 32) ? tokens[b * SEQ + 32 + lane] : 0;

            int toks[13];
            #pragma unroll
            for (int i = 0; i < 12; i++) {
                int idx = 4 * i + grp;
                toks[i] = (i < 8) ? __shfl_sync(0xffffffffu, t0, idx)
                                  : __shfl_sync(0xffffffffu, t1, idx - 32);
            }
            toks[12] = __shfl_sync(0xffffffffu, t1, 16 + (grp & 1));

            uint2 r[13];
            #pragma unroll
            for (int i = 0; i < 12; i++)
                r[i] = __ldg(&E2v[(size_t)toks[i] * 8 + hp]);
            r[12] = (grp < 2) ? __ldg(&E2v[(size_t)toks[12] * 8 + hp])
                              : make_uint2(0u, 0u);

            float4 acc = make_float4(0.f, 0.f, 0.f, 0.f);
            #pragma unroll
            for (int i = 0; i < 13; i++) {
                float2 lo = __bfloat1622float2(*reinterpret_cast<__nv_bfloat162*>(&r[i].x));
                float2 hi = __bfloat1622float2(*reinterpret_cast<__nv_bfloat162*>(&r[i].y));
                acc.x += lo.x; acc.y += lo.y; acc.z += hi.x; acc.w += hi.y;
            }
            #pragma unroll
            for (int off = 8; off <= 16; off <<= 1) {
                acc.x += __shfl_xor_sync(0xffffffffu, acc.x, off);
                acc.y += __shfl_xor_sync(0xffffffffu, acc.y, off);
                acc.z += __shfl_xor_sync(0xffffffffu, acc.z, off);
                acc.w += __shfl_xor_sync(0xffffffffu, acc.w, off);
            }

            const float inv = 1.0f / (float)SEQ;
            float4 vb = ((const float4*)Vb)[hp];
            float h0 = fmaxf(acc.x * inv + vb.x, 0.f);
            float h1 = fmaxf(acc.y * inv + vb.y, 0.f);
            float h2 = fmaxf(acc.z * inv + vb.z, 0.f);
            float h3 = fmaxf(acc.w * inv + vb.w, 0.f);

            float4 w0 = ((const float4*)Ww)[hp];
            float4 w1 = ((const float4*)(Ww + HID))[hp];
            float p0 = h0 * w0.x + h1 * w0.y + h2 * w0.z + h3 * w0.w;
            float p1 = h0 * w1.x + h1 * w1.y + h2 * w1.z + h3 * w1.w;
            #pragma unroll
            for (int off = 4; off; off >>= 1) {
                p0 += __shfl_xor_sync(0xffffffffu, p0, off);
                p1 += __shfl_xor_sync(0xffffffffu, p1, off);
            }

            if (lane == 0) {
                float e0 = p0 + Wb[0];
                float e1 = p1 + Wb[1];
                out[b * OUTC + 0] = e0;
                out[b * OUTC + 1] = e1;
                float nm0 = fmaxf(m0, e0);
                ss0 = ss0 * expf(m0 - nm0) + expf(e0 - nm0);
                m0  = nm0;
                float nm1 = fmaxf(m1, e1);
                ss1 = ss1 * expf(m1 - nm1) + expf(e1 - nm1);
                m1  = nm1;
            }
        }

        if (lane == 0) sPart[warp] = make_float4(m0, m1, ss0, ss1);
        __syncthreads();

        // warp 0 merges the 8 warp partials (shuffle tree) -> g_part[bid]
        if (warp == 0) {
            float4 a = (lane < 8) ? sPart[lane] : make_float4(-1e30f, -1e30f, 0.f, 0.f);
            float M0 = a.x, M1 = a.y;
            #pragma unroll
            for (int off = 4; off; off >>= 1) {
                M0 = fmaxf(M0, __shfl_xor_sync(0xffffffffu, M0, off));
                M1 = fmaxf(M1, __shfl_xor_sync(0xffffffffu, M1, off));
            }
            float S0 = a.z * expf(a.x - M0);
            float S1 = a.w * expf(a.y - M1);
            #pragma unroll
            for (int off = 4; off; off >>= 1) {
                S0 += __shfl_xor_sync(0xffffffffu, S0, off);
                S1 += __shfl_xor_sync(0xffffffffu, S1, off);
            }
            if (lane == 0) g_part[bid] = make_float4(M0, M1, S0, S1);
        }
    }

    // ===================== Barrier 2: partials complete =====================
    grid_barrier(&g_cnt2, &g_epoch2);

    // ===================== Phase 3: global LSE (redundant) + apply ==========
    {
        // every CTA reduces the 148 partials in the SAME fixed order
        if (warp == 0) {
            float4 p[5];
            float M0 = -1e30f, M1 = -1e30f;
            #pragma unroll
            for (int j = 0; j < 5; j++) {
                int idx = lane + 32 * j;
                p[j] = (idx < GRID) ? g_part[idx]
                                    : make_float4(-1e30f, -1e30f, 0.f, 0.f);
                M0 = fmaxf(M0, p[j].x);
                M1 = fmaxf(M1, p[j].y);
            }
            #pragma unroll
            for (int off = 16; off; off >>= 1) {
                M0 = fmaxf(M0, __shfl_xor_sync(0xffffffffu, M0, off));
                M1 = fmaxf(M1, __shfl_xor_sync(0xffffffffu, M1, off));
            }
            float S0 = 0.f, S1 = 0.f;
            #pragma unroll
            for (int j = 0; j < 5; j++) {
                S0 += p[j].z * expf(p[j].x - M0);
                S1 += p[j].w * expf(p[j].y - M1);
            }
            #pragma unroll
            for (int off = 16; off; off >>= 1) {
                S0 += __shfl_xor_sync(0xffffffffu, S0, off);
                S1 += __shfl_xor_sync(0xffffffffu, S1, off);
            }
            if (lane == 0) {
                sLse[0] = M0 + logf(S0);
                sLse[1] = M1 + logf(S1);
            }
        }
        __syncthreads();
        const float l0 = sLse[0];
        const float l1 = sLse[1];

        for (int i = bid * 256 + tid; i < BATCH; i += GRID * 256) {
            float2 v = reinterpret_cast<float2*>(out)[i];
            v.x -= l0;
            v.y -= l1;
            reinterpret_cast<float2*>(out)[i] = v;
        }
    }
}

extern "C" void kernel_launch(void* const* d_in, const int* in_sizes, int n_in,
                              void* d_out, int out_size)
{
    const int*   tokens = (const int*)  d_in[0];
    const float* emb    = (const float*)d_in[1];
    const float* Vw     = (const float*)d_in[2];
    const float* Vb     = (const float*)d_in[3];
    const float* Ww     = (const float*)d_in[4];
    const float* Wb     = (const float*)d_in[5];
    float* out = (float*)d_out;

    cudaFuncSetAttribute(dan_fused,
                         cudaFuncAttributeMaxDynamicSharedMemorySize, SMEM_BYTES);

    dan_fused<<<GRID, 256, SMEM_BYTES>>>(emb, Vw, tokens, Vb, Ww, Wb, out);
}

// round 17
// speedup vs baseline: 1.0790x; 1.0790x over previous
#include <cuda_runtime.h>
#include <cuda_bf16.h>
#include <math.h>
#include <stdint.h>

#define BATCH 16384
#define SEQ   50
#define DIM   300
#define HID   32
#define OUTC  2
#define VOCAB 400000

// allocation-free scratch
__device__ uint32_t g_E2[(size_t)VOCAB * (HID / 2)];   // bf16x2 table, 25.6 MB
__device__ float4   g_part[296];                       // per-CTA {m0,m1,s0,s1}
__device__ float    g_lse[2];                          // global logsumexp
__device__ unsigned g_done;                            // gather completion ctr

// ---------------------------------------------------------------------------
// Pass A: E2[v][j] = sum_d emb[v][d] * Vw[j][d]   (400000x300 @ 300x32)
// tf32 mma.sync, 5-stage cp.async.bulk ring, 148 persistent CTAs x 256 thr,
// B fragments in registers, bf16x2 output. emb loads L2::evict_first,
// E2 stores L2::evict_last. (At its HBM floor: ~480MB emb stream @ ~6.3TB/s.)
// ---------------------------------------------------------------------------
#define TILE_R     32
#define KSTEPS     38
#define NT32       (VOCAB / TILE_R)          // 12500 tiles
#define GRID       148
#define NSTAGE     5
#define TILE_ELEMS (TILE_R * DIM)            // 9600 floats
#define TILE_BYTES (TILE_ELEMS * 4)          // 38400 B
#define PAD_ELEMS  16
#define MBAR_OFF   (NSTAGE * TILE_ELEMS + PAD_ELEMS)
#define SMEM_BYTES ((MBAR_OFF + 20) * 4)

#define GGRID      296                       // gather grid (2 CTAs/SM)
#define GWARPS     (GGRID * 16)              // 4736 warps total

__device__ __forceinline__ uint32_t smem_u32(const void* p) {
    return (uint32_t)__cvta_generic_to_shared(p);
}
__device__ __forceinline__ void mbar_init(uint32_t mbar, uint32_t cnt) {
    asm volatile("mbarrier.init.shared::cta.b64 [%0], %1;" :: "r"(mbar), "r"(cnt) : "memory");
}
__device__ __forceinline__ void mbar_expect_tx(uint32_t mbar, uint32_t bytes) {
    asm volatile("mbarrier.arrive.expect_tx.shared::cta.b64 _, [%0], %1;"
                 :: "r"(mbar), "r"(bytes) : "memory");
}
__device__ __forceinline__ void mbar_arrive(uint32_t mbar) {
    asm volatile("mbarrier.arrive.release.cta.shared::cta.b64 _, [%0];"
                 :: "r"(mbar) : "memory");
}
__device__ __forceinline__ void mbar_wait(uint32_t mbar, uint32_t parity) {
    asm volatile(
        "{\n\t"
        ".reg .pred P;\n\t"
        "WAIT_%=: \n\t"
        "mbarrier.try_wait.parity.acquire.cta.shared::cta.b64 P, [%0], %1, 0x989680;\n\t"
        "@P bra.uni DONE_%=;\n\t"
        "bra.uni WAIT_%=;\n\t"
        "DONE_%=: \n\t"
        "}"
        :: "r"(mbar), "r"(parity) : "memory");
}
__device__ __forceinline__ uint64_t policy_evict_first() {
    uint64_t pol;
    asm("createpolicy.fractional.L2::evict_first.b64 %0, 1.0;" : "=l"(pol));
    return pol;
}
__device__ __forceinline__ uint64_t policy_evict_last() {
    uint64_t pol;
    asm("createpolicy.fractional.L2::evict_last.b64 %0, 1.0;" : "=l"(pol));
    return pol;
}
__device__ __forceinline__ void bulk_copy_hint(uint32_t dst, const void* src,
                                               uint32_t bytes, uint32_t mbar,
                                               uint64_t pol) {
    asm volatile(
        "cp.async.bulk.shared::cta.global.mbarrier::complete_tx::bytes.L2::cache_hint "
        "[%0], [%1], %2, [%3], %4;"
        :: "r"(dst), "l"(src), "r"(bytes), "r"(mbar), "l"(pol) : "memory");
}
__device__ __forceinline__ void st_hint(uint32_t* p, uint32_t v, uint64_t pol) {
    asm volatile("st.global.L2::cache_hint.b32 [%0], %1, %2;"
                 :: "l"(p), "r"(v), "l"(pol) : "memory");
}
__device__ __forceinline__ void mma_tf32(
    float acc[4], uint32_t a0, uint32_t a1, uint32_t a2, uint32_t a3,
    uint32_t b0, uint32_t b1)
{
    asm volatile(
        "mma.sync.aligned.m16n8k8.row.col.f32.tf32.tf32.f32 "
        "{%0,%1,%2,%3}, {%4,%5,%6,%7}, {%8,%9}, {%0,%1,%2,%3};\n"
        : "+f"(acc[0]), "+f"(acc[1]), "+f"(acc[2]), "+f"(acc[3])
        : "r"(a0), "r"(a1), "r"(a2), "r"(a3), "r"(b0), "r"(b1));
}
__device__ __forceinline__ uint32_t pack_bf16x2(float lo, float hi) {
    __nv_bfloat162 v = __float22bfloat162_rn(make_float2(lo, hi));
    return *reinterpret_cast<uint32_t*>(&v);
}

__global__ __launch_bounds__(256) void project_kernel(
    const float* __restrict__ emb,
    const float* __restrict__ Vw)
{
    extern __shared__ float smem[];
    const uint32_t mbarBase  = smem_u32(smem + MBAR_OFF);   // full[0..4]
    const uint32_t emptyBase = mbarBase + NSTAGE * 8;       // empty[0..4]

    const int tid  = threadIdx.x;
    const int warp = tid >> 5;
    const int lane = tid & 31;
    const int g4   = lane >> 2;
    const int tg   = lane & 3;

    const int warpRow = warp >> 2;
    const int colQuad = warp & 3;
    const int aRow    = warpRow * 16 + g4;

    if (blockIdx.x == 0 && tid == 0) g_done = 0;   // reset gather's counter

    const uint64_t polF = policy_evict_first();
    const uint64_t polL = policy_evict_last();

    if (tid == 0) {
        #pragma unroll
        for (int i = 0; i < NSTAGE; i++) {
            mbar_init(mbarBase  + i * 8, 1);
            mbar_init(emptyBase + i * 8, 8);
        }
        asm volatile("fence.proxy.async.shared::cta;" ::: "memory");
    }
    if (tid < PAD_ELEMS)
        smem[NSTAGE * TILE_ELEMS + tid] = 0.0f;
    __syncthreads();

    const int bid = blockIdx.x;

    if (tid == 0) {
        #pragma unroll
        for (int s = 0; s < NSTAGE; s++) {
            int tt = bid + s * GRID;
            if (tt < NT32) {
                mbar_expect_tx(mbarBase + s * 8, TILE_BYTES);
                bulk_copy_hint(smem_u32(smem + s * TILE_ELEMS),
                               emb + (size_t)tt * TILE_ELEMS, TILE_BYTES,
                               mbarBase + s * 8, polF);
            }
        }
    }

    // B fragments straight from gmem into registers (once)
    uint2 breg[KSTEPS];
    {
        const int n = colQuad * 8 + g4;
        const float* vwr = Vw + n * DIM;
        #pragma unroll
        for (int ks = 0; ks < KSTEPS; ks++) {
            int k = ks * 8 + tg;
            breg[ks].x = (k     < DIM) ? __float_as_uint(vwr[k])     : 0u;
            breg[ks].y = (k + 4 < DIM) ? __float_as_uint(vwr[k + 4]) : 0u;
        }
    }

    uint32_t ph0 = 0, ph1 = 0, ph2 = 0, ph3 = 0, ph4 = 0;
    uint32_t pe0 = 0, pe1 = 0, pe2 = 0, pe3 = 0, pe4 = 0;

    int t = bid;
    while (t < NT32) {
        #pragma unroll
        for (int s = 0; s < NSTAGE; s++) {
            if (t < NT32) {
                const uint32_t fullb  = mbarBase  + s * 8;
                const uint32_t emptyb = emptyBase + s * 8;

                uint32_t phv = (s == 0) ? ph0 : (s == 1) ? ph1 : (s == 2) ? ph2
                             : (s == 3) ? ph3 : ph4;
                mbar_wait(fullb, phv);
                if      (s == 0) ph0 ^= 1;
                else if (s == 1) ph1 ^= 1;
                else if (s == 2) ph2 ^= 1;
                else if (s == 3) ph3 ^= 1;
                else             ph4 ^= 1;

                const uint32_t* A =
                    (const uint32_t*)(smem + s * TILE_ELEMS) + aRow * DIM + tg;

                float accE[4] = {0.f, 0.f, 0.f, 0.f};
                float accO[4] = {0.f, 0.f, 0.f, 0.f};

                #pragma unroll
                for (int ks = 0; ks < KSTEPS; ks += 2) {
                    {
                        const uint32_t* Ap = A + ks * 8;
                        mma_tf32(accE, Ap[0], Ap[8 * DIM], Ap[4], Ap[8 * DIM + 4],
                                 breg[ks].x, breg[ks].y);
                    }
                    {
                        const uint32_t* Ap = A + (ks + 1) * 8;
                        mma_tf32(accO, Ap[0], Ap[8 * DIM], Ap[4], Ap[8 * DIM + 4],
                                 breg[ks + 1].x, breg[ks + 1].y);
                    }
                }

                if (lane == 0) mbar_arrive(emptyb);

                int r0  = t * TILE_R + warpRow * 16 + g4;
                int cp  = colQuad * 4 + tg;
                st_hint(&g_E2[(size_t)r0 * (HID / 2) + cp],
                        pack_bf16x2(accE[0] + accO[0], accE[1] + accO[1]), polL);
                st_hint(&g_E2[(size_t)(r0 + 8) * (HID / 2) + cp],
                        pack_bf16x2(accE[2] + accO[2], accE[3] + accO[3]), polL);

                int tload = t + NSTAGE * GRID;
                if (tid == 0 && tload < NT32) {
                    uint32_t pev = (s == 0) ? pe0 : (s == 1) ? pe1 : (s == 2) ? pe2
                                 : (s == 3) ? pe3 : pe4;
                    mbar_wait(emptyb, pev);
                    if      (s == 0) pe0 ^= 1;
                    else if (s == 1) pe1 ^= 1;
                    else if (s == 2) pe2 ^= 1;
                    else if (s == 3) pe3 ^= 1;
                    else             pe4 ^= 1;
                    mbar_expect_tx(fullb, TILE_BYTES);
                    bulk_copy_hint(smem_u32(smem + s * TILE_ELEMS),
                                   emb + (size_t)tload * TILE_ELEMS, TILE_BYTES,
                                   fullb, polF);
                }
                t += GRID;
            }
        }
    }
}

// ---------------------------------------------------------------------------
// Pass B: persistent gather. 296 CTAs x 512 thr (2 CTAs/SM, 32 warps/SM).
// Each warp owns 3-4 rows (stride 4736). ALL of the warp's token words are
// prefetched up front (MLP=8, one DRAM trip instead of one per row); per row
// the 13 E2 loads are batched (MLP=13). Per-warp online LSE -> warp-0 merge
// -> g_part[296]; last CTA reduces to g_lse (fixed order, deterministic).
// ---------------------------------------------------------------------------
__global__ __launch_bounds__(512, 2) void gather_kernel(
    const int*   __restrict__ tokens,
    const float* __restrict__ Vb,
    const float* __restrict__ Ww,
    const float* __restrict__ Wb,
    float*       __restrict__ out)
{
    __shared__ float4 sE[16];
    __shared__ bool   sLast;

    const int warp = threadIdx.x >> 5;          // 0..15
    const int lane = threadIdx.x & 31;
    const int grp  = lane >> 3;
    const int hp   = lane & 7;
    const int wg   = blockIdx.x * 16 + warp;    // warp-global id, 0..4735

    const uint2* E2v = (const uint2*)g_E2;      // 8 uint2 per row

    // ---- prefetch ALL token words for this warp's rows (MLP = 2*nr) ----
    const int nr = (wg + 3 * GWARPS < BATCH) ? 4 : 3;
    int t0[4], t1[4];
    #pragma unroll
    for (int j = 0; j < 4; j++) {
        if (j < nr) {
            int b = wg + j * GWARPS;
            t0[j] = __ldg(&tokens[b * SEQ + lane]);
            t1[j] = (lane < SEQ - 32) ? __ldg(&tokens[b * SEQ + 32 + lane]) : 0;
        }
    }

    // per-warp online LSE (meaningful at lane 0; fixed order -> deterministic)
    float m0 = -1e30f, m1 = -1e30f, ss0 = 0.f, ss1 = 0.f;

    const float inv = 1.0f / (float)SEQ;
    const float4 vb = ((const float4*)Vb)[hp];
    const float4 w0 = ((const float4*)Ww)[hp];
    const float4 w1 = ((const float4*)(Ww + HID))[hp];
    const float  wb0 = Wb[0], wb1 = Wb[1];

    #pragma unroll
    for (int j = 0; j < 4; j++) {
        if (j < nr) {
            const int b = wg + j * GWARPS;

            int toks[13];
            #pragma unroll
            for (int i = 0; i < 12; i++) {
                int idx = 4 * i + grp;
                toks[i] = (i < 8) ? __shfl_sync(0xffffffffu, t0[j], idx)
                                  : __shfl_sync(0xffffffffu, t1[j], idx - 32);
            }
            toks[12] = __shfl_sync(0xffffffffu, t1[j], 16 + (grp & 1));

            uint2 r[13];
            #pragma unroll
            for (int i = 0; i < 12; i++)
                r[i] = __ldg(&E2v[(size_t)toks[i] * 8 + hp]);
            r[12] = (grp < 2) ? __ldg(&E2v[(size_t)toks[12] * 8 + hp])
                              : make_uint2(0u, 0u);

            float4 acc = make_float4(0.f, 0.f, 0.f, 0.f);
            #pragma unroll
            for (int i = 0; i < 13; i++) {
                float2 lo = __bfloat1622float2(*reinterpret_cast<__nv_bfloat162*>(&r[i].x));
                float2 hi = __bfloat1622float2(*reinterpret_cast<__nv_bfloat162*>(&r[i].y));
                acc.x += lo.x; acc.y += lo.y; acc.z += hi.x; acc.w += hi.y;
            }
            #pragma unroll
            for (int off = 8; off <= 16; off <<= 1) {
                acc.x += __shfl_xor_sync(0xffffffffu, acc.x, off);
                acc.y += __shfl_xor_sync(0xffffffffu, acc.y, off);
                acc.z += __shfl_xor_sync(0xffffffffu, acc.z, off);
                acc.w += __shfl_xor_sync(0xffffffffu, acc.w, off);
            }

            float h0 = fmaxf(acc.x * inv + vb.x, 0.f);
            float h1 = fmaxf(acc.y * inv + vb.y, 0.f);
            float h2 = fmaxf(acc.z * inv + vb.z, 0.f);
            float h3 = fmaxf(acc.w * inv + vb.w, 0.f);

            float p0 = h0 * w0.x + h1 * w0.y + h2 * w0.z + h3 * w0.w;
            float p1 = h0 * w1.x + h1 * w1.y + h2 * w1.z + h3 * w1.w;
            #pragma unroll
            for (int off = 4; off; off >>= 1) {
                p0 += __shfl_xor_sync(0xffffffffu, p0, off);
                p1 += __shfl_xor_sync(0xffffffffu, p1, off);
            }

            if (lane == 0) {
                float e0 = p0 + wb0;
                float e1 = p1 + wb1;
                out[b * OUTC + 0] = e0;
                out[b * OUTC + 1] = e1;
                float nm0 = fmaxf(m0, e0);
                ss0 = ss0 * expf(m0 - nm0) + expf(e0 - nm0);
                m0  = nm0;
                float nm1 = fmaxf(m1, e1);
                ss1 = ss1 * expf(m1 - nm1) + expf(e1 - nm1);
                m1  = nm1;
            }
        }
    }

    if (lane == 0) sE[warp] = make_float4(m0, m1, ss0, ss1);
    __syncthreads();

    // warp 0 merges the 16 warp partials -> g_part[bid]
    if (warp == 0) {
        float4 a = (lane < 16) ? sE[lane] : make_float4(-1e30f, -1e30f, 0.f, 0.f);
        float M0 = a.x, M1 = a.y;
        #pragma unroll
        for (int off = 8; off; off >>= 1) {
            M0 = fmaxf(M0, __shfl_xor_sync(0xffffffffu, M0, off));
            M1 = fmaxf(M1, __shfl_xor_sync(0xffffffffu, M1, off));
        }
        float S0 = a.z * expf(a.x - M0);
        float S1 = a.w * expf(a.y - M1);
        #pragma unroll
        for (int off = 8; off; off >>= 1) {
            S0 += __shfl_xor_sync(0xffffffffu, S0, off);
            S1 += __shfl_xor_sync(0xffffffffu, S1, off);
        }
        if (lane == 0) g_part[blockIdx.x] = make_float4(M0, M1, S0, S1);
    }
    __syncthreads();

    // completion counter; last CTA computes the LSE scalars only
    if (threadIdx.x == 0) {
        __threadfence();
        unsigned n = atomicAdd(&g_done, 1u);
        sLast = (n == (unsigned)(gridDim.x - 1));
    }
    __syncthreads();
    if (!sLast) return;

    __threadfence();

    // warp 0: reduce 296 partials (10 strided chunks, fixed order)
    if (warp == 0) {
        float4 p[10];
        float M0 = -1e30f, M1 = -1e30f;
        #pragma unroll
        for (int j = 0; j < 10; j++) {
            int idx = lane + 32 * j;
            p[j] = (idx < GGRID) ? g_part[idx]
                                 : make_float4(-1e30f, -1e30f, 0.f, 0.f);
            M0 = fmaxf(M0, p[j].x);
            M1 = fmaxf(M1, p[j].y);
        }
        #pragma unroll
        for (int off = 16; off; off >>= 1) {
            M0 = fmaxf(M0, __shfl_xor_sync(0xffffffffu, M0, off));
            M1 = fmaxf(M1, __shfl_xor_sync(0xffffffffu, M1, off));
        }
        float S0 = 0.f, S1 = 0.f;
        #pragma unroll
        for (int j = 0; j < 10; j++) {
            S0 += p[j].z * expf(p[j].x - M0);
            S1 += p[j].w * expf(p[j].y - M1);
        }
        #pragma unroll
        for (int off = 16; off; off >>= 1) {
            S0 += __shfl_xor_sync(0xffffffffu, S0, off);
            S1 += __shfl_xor_sync(0xffffffffu, S1, off);
        }
        if (lane == 0) {
            g_lse[0] = M0 + logf(S0);
            g_lse[1] = M1 + logf(S1);
        }
    }
}

// ---------------------------------------------------------------------------
// Pass C: wide parallel apply: out[b,c] -= lse[c]. 16 CTAs x 512, float4.
// ---------------------------------------------------------------------------
__global__ __launch_bounds__(512) void apply_kernel(float* __restrict__ out)
{
    const float l0 = g_lse[0];
    const float l1 = g_lse[1];
    const int   i  = blockIdx.x * 512 + threadIdx.x;   // 8192 float4 total
    float4 v = reinterpret_cast<float4*>(out)[i];
    v.x -= l0; v.y -= l1; v.z -= l0; v.w -= l1;
    reinterpret_cast<float4*>(out)[i] = v;
}

extern "C" void kernel_launch(void* const* d_in, const int* in_sizes, int n_in,
                              void* d_out, int out_size)
{
    const int*   tokens = (const int*)  d_in[0];
    const float* emb    = (const float*)d_in[1];
    const float* Vw     = (const float*)d_in[2];
    const float* Vb     = (const float*)d_in[3];
    const float* Ww     = (const float*)d_in[4];
    const float* Wb     = (const float*)d_in[5];
    float* out = (float*)d_out;

    cudaFuncSetAttribute(project_kernel,
                         cudaFuncAttributeMaxDynamicSharedMemorySize, SMEM_BYTES);

    project_kernel<<<GRID, 256, SMEM_BYTES>>>(emb, Vw);
    gather_kernel<<<GGRID, 512>>>(tokens, Vb, Ww, Wb, out);
    apply_kernel<<<16, 512>>>(out);
}